// round 10
// baseline (speedup 1.0000x reference)
#include <cuda_runtime.h>
#include <cuda_fp16.h>

// ---------------------------------------------------------------------------
// Popcnt_14731737825611 — R6: warp-specialized hybrid gather.
// Per CTA: 24 "S" warps gather from a 128KB smem batch-slice (crossbar pipe),
// 8 "G" warps do warp-uniform full-row gathers from L2 (LTS pipe). The two
// memory pipes run concurrently. Activations kept in BOTH row-major (for G)
// and column-blocked [32][rows][8] (for coalesced smem staging) layouts.
// LayerNorm folded into weights (C1/C2); deterministic partial-sum LN;
// final group-sum fused into all-smem layer 3.
// ---------------------------------------------------------------------------

namespace {
constexpr int B     = 256;
constexpr int IN1   = 3200;
constexpr int O1    = 8192;
constexpr int O3    = 4096;
constexpr int P     = 128;
constexpr int OS12  = 3072;              // smem-path outputs, layers 1/2
constexpr int OG12  = O1 - OS12;         // 5120 L2-path outputs
constexpr int CHO12 = 768;               // S outputs per chunk (layers 1/2)
constexpr int CHO3  = 1024;              // layer 3 (all-S)
constexpr int NCTA  = 128;
constexpr int WS    = 24;                // S warps per CTA
constexpr int WG    = 8;                 // G warps per CTA
constexpr int GPER  = OG12 / (NCTA * WG); // 5 outputs per G warp
}

// Activations: row-major (G gathers) + column-blocked [32][rows][8] (staging).
__device__ __half g_xT [IN1 * B];
__device__ __half g_xB [IN1 * B];
__device__ __half g_h1 [O1 * B];
__device__ __half g_h1B[O1 * B];
__device__ __half g_h2 [O1 * B];
__device__ __half g_h2B[O1 * B];
// Pair tables: S region transposed [chunk][quad][o_local]; G region row-major.
__device__ uint4 g_pkS1[OS12 * 32];
__device__ uint4 g_pkG1[OG12 * 32];
__device__ uint4 g_pkS2[OS12 * 32];
__device__ uint4 g_pkG2[OG12 * 32];
__device__ uint4 g_pkS3[O3 * 32];
// LN constants + partials.
__device__ float g_C1b[O1], g_C2b[O1], g_C1c[O3], g_C2c[O3];
__device__ float g_psS[4 * B], g_pqS[4 * B];
__device__ float g_psG[NCTA * B], g_pqG[NCTA * B];
__device__ float g_mu[2][B], g_rs[2][B];

__device__ __forceinline__ float sigmoidf_fast(float x) {
    return 1.0f / (1.0f + __expf(-x));
}
__device__ __forceinline__ unsigned pack_pair(int idx, float w) {
    __half h = __float2half_rn(w);
    return (unsigned)idx | ((unsigned)__half_as_ushort(h) << 16);
}
__device__ __forceinline__ void fma8(const uint4 v, const float wv, float* acc) {
    float2 f;
    f = __half22float2(*(const __half2*)&v.x); acc[0] = fmaf(wv, f.x, acc[0]); acc[1] = fmaf(wv, f.y, acc[1]);
    f = __half22float2(*(const __half2*)&v.y); acc[2] = fmaf(wv, f.x, acc[2]); acc[3] = fmaf(wv, f.y, acc[3]);
    f = __half22float2(*(const __half2*)&v.z); acc[4] = fmaf(wv, f.x, acc[4]); acc[5] = fmaf(wv, f.y, acc[5]);
    f = __half22float2(*(const __half2*)&v.w); acc[6] = fmaf(wv, f.x, acc[6]); acc[7] = fmaf(wv, f.y, acc[7]);
}
__device__ __forceinline__ uint4 pack_h8(const float* h) {
    uint4 ov; __half2 hh;
    hh = __floats2half2_rn(h[0], h[1]); ov.x = *(unsigned*)&hh;
    hh = __floats2half2_rn(h[2], h[3]); ov.y = *(unsigned*)&hh;
    hh = __floats2half2_rn(h[4], h[5]); ov.z = *(unsigned*)&hh;
    hh = __floats2half2_rn(h[6], h[7]); ov.w = *(unsigned*)&hh;
    return ov;
}

// --- transpose x[B, IN1] -> g_xT row-major + g_xB blocked ------------------
__global__ void k_transpose(const float* __restrict__ x) {
    __shared__ float t[32][33];
    const int i0 = blockIdx.x * 32;
    const int b0 = blockIdx.y * 32;
    const int tx = threadIdx.x, ty = threadIdx.y;
#pragma unroll
    for (int j = 0; j < 32; j += 8)
        t[ty + j][tx] = x[(b0 + ty + j) * IN1 + (i0 + tx)];
    __syncthreads();
#pragma unroll
    for (int j = 0; j < 32; j += 8) {
        const int i = i0 + ty + j, b = b0 + tx;
        const __half h = __float2half_rn(t[tx][ty + j]);
        g_xT[i * B + b] = h;
        g_xB[(b >> 3) * (IN1 * 8) + i * 8 + (b & 7)] = h;
    }
}

// --- merged prep: pack pair tables (S transposed / G row-major), C1/C2 -----
__global__ void __launch_bounds__(1024) k_prep(
    const int* __restrict__ sel1, const float* __restrict__ w1,
    const int* __restrict__ sel2, const float* __restrict__ w2,
    const float* __restrict__ g1v, const float* __restrict__ be1,
    const int* __restrict__ sel3, const float* __restrict__ w3,
    const float* __restrict__ g2v, const float* __restrict__ be2)
{
    __shared__ unsigned tile[128][33];
    const int blk = blockIdx.x;
    int layer, o0;
    const int* sel; const float* w; const float* gm; const float* bt_;
    if (blk < 256)      { layer = 1; o0 = blk * 32;         sel = sel1; w = w1; gm = nullptr; bt_ = nullptr; }
    else if (blk < 512) { layer = 2; o0 = (blk - 256) * 32; sel = sel2; w = w2; gm = g1v;    bt_ = be1; }
    else                { layer = 3; o0 = (blk - 512) * 32; sel = sel3; w = w3; gm = g2v;    bt_ = be2; }

    const int wid = threadIdx.x >> 5, lane = threadIdx.x & 31;
    const int o = o0 + wid;
    const int4   s4 = reinterpret_cast<const int4*>(sel + o * P)[lane];
    const float4 w4 = reinterpret_cast<const float4*>(w   + o * P)[lane];
    const int   idx[4] = { s4.x, s4.y, s4.z, s4.w };
    const float sg[4]  = { sigmoidf_fast(w4.x), sigmoidf_fast(w4.y),
                           sigmoidf_fast(w4.z), sigmoidf_fast(w4.w) };
    unsigned pk[4];
    float c1 = 0.f, c2 = 0.f;
#pragma unroll
    for (int j = 0; j < 4; ++j) {
        float sw = sg[j];
        if (layer > 1) {
            sw *= __ldg(gm + idx[j]);
            c1 += sw;
            c2 = fmaf(sg[j], __ldg(bt_ + idx[j]), c2);
        }
        pk[j] = pack_pair(idx[j], sw);
    }
    if (layer > 1) {
#pragma unroll
        for (int st = 16; st > 0; st >>= 1) {
            c1 += __shfl_xor_sync(0xffffffffu, c1, st);
            c2 += __shfl_xor_sync(0xffffffffu, c2, st);
        }
        if (lane == 0) {
            if (layer == 2) { g_C1b[o] = c1; g_C2b[o] = c2; }
            else            { g_C1c[o] = c1; g_C2c[o] = c2; }
        }
    }

    const bool transposed = (layer == 3) || (o0 < OS12);
    if (transposed) {
#pragma unroll
        for (int j = 0; j < 4; ++j) tile[lane * 4 + j][wid] = pk[j];
        __syncthreads();
        uint4 ov;
        ov.x = tile[wid * 4 + 0][lane];
        ov.y = tile[wid * 4 + 1][lane];
        ov.z = tile[wid * 4 + 2][lane];
        ov.w = tile[wid * 4 + 3][lane];
        uint4* pkS = (layer == 1) ? g_pkS1 : (layer == 2) ? g_pkS2 : g_pkS3;
        const int CHO = (layer == 3) ? CHO3 : CHO12;
        const int c = o0 / CHO, ob = o0 % CHO;
        pkS[c * (32 * CHO) + wid * CHO + ob + lane] = ov;
    } else {
        uint4* pkG = (layer == 1) ? g_pkG1 : g_pkG2;
        pkG[(o - OS12) * 32 + lane] = make_uint4(pk[0], pk[1], pk[2], pk[3]);
    }
}

// --- hybrid popcnt layer ----------------------------------------------------
template <int L>
__global__ void __launch_bounds__(1024, 1) k_pop(const float* __restrict__ bias,
                                                 float* __restrict__ out)
{
    constexpr int NR   = (L == 1) ? IN1 : O1;
    constexpr bool HYB = (L < 3);
    constexpr int CHO  = (L == 3) ? CHO3 : CHO12;
    constexpr int OOUT = O1;                       // rows of output tables (L<3)

    extern __shared__ uint4 sl[];                  // NR slices of 16B
    __shared__ float smu[B], srs[B];
    __shared__ float sGs[WG][B], sGq[WG][B];
    __shared__ float sSs[WS][8], sSq[WS][8];

    const __half* inRow = (L == 1) ? g_xT : (L == 2) ? g_h1 : g_h2;
    const __half* inBlk = (L == 1) ? g_xB : (L == 2) ? g_h1B : g_h2B;
    __half* outR = (L == 1) ? g_h1  : g_h2;
    __half* outB = (L == 1) ? g_h1B : g_h2B;
    const uint4* pkS = (L == 1) ? g_pkS1 : (L == 2) ? g_pkS2 : g_pkS3;
    const uint4* pkG = (L == 1) ? g_pkG1 : g_pkG2;

    const int blk = blockIdx.x;
    const int bt  = blk & 31;          // btile: columns bt*8..bt*8+7
    const int c   = blk >> 5;          // output chunk
    const int tid = threadIdx.x, wid = tid >> 5, lane = tid & 31;

    // stage slice (coalesced from blocked layout)
    {
        const uint4* src = reinterpret_cast<const uint4*>(inBlk) + bt * NR;
        for (int r = tid; r < NR; r += 1024) sl[r] = __ldg(src + r);
    }
    if (L > 1 && tid < B) { smu[tid] = g_mu[L - 2][tid]; srs[tid] = g_rs[L - 2][tid]; }
    __syncthreads();

    if (!HYB || wid < WS) {
        // ---- S path: thread = 1 output x 8 smem columns ----
        const int ol = tid;                    // < WS*32 (HYB) or < 1024 (L3)
        const int o  = c * CHO + ol;
        const uint4* pp = pkS + c * (32 * CHO) + ol;
        float acc[8];
#pragma unroll
        for (int j = 0; j < 8; ++j) acc[j] = 0.f;

        uint4 qd = __ldcg(pp);
#pragma unroll 2
        for (int q = 0; q < 32; ++q) {
            const uint4 qn = __ldcg(pp + ((q + 1) & 31) * CHO);
            const unsigned pc[4] = { qd.x, qd.y, qd.z, qd.w };
            uint4 v[4];
#pragma unroll
            for (int j = 0; j < 4; ++j) v[j] = sl[pc[j] & 0xFFFFu];
#pragma unroll
            for (int j = 0; j < 4; ++j) {
                const float wv = __half2float(__ushort_as_half((unsigned short)(pc[j] >> 16)));
                fma8(v[j], wv, acc);
            }
            qd = qn;
        }

        const float bo = __ldg(bias + o);
        float c1 = 0.f, c2v = 0.f;
        if (L > 1) { c1 = ((L == 2) ? g_C1b : g_C1c)[o]; c2v = ((L == 2) ? g_C2b : g_C2c)[o]; }
        float h[8];
#pragma unroll
        for (int j = 0; j < 8; ++j) {
            const float pre = (L > 1)
                ? (fmaf(srs[bt * 8 + j], acc[j] - smu[bt * 8 + j] * c1, c2v) - bo)
                : (acc[j] - bo);
            h[j] = sigmoidf_fast(pre);
        }

        if (L < 3) {
            const uint4 ov = pack_h8(h);
            *reinterpret_cast<uint4*>(outR + o * B + bt * 8) = ov;
            reinterpret_cast<uint4*>(outB)[bt * OOUT + o] = ov;
            // LN partial (warp tree)
            float s[8], q8[8];
#pragma unroll
            for (int j = 0; j < 8; ++j) { s[j] = h[j]; q8[j] = h[j] * h[j]; }
#pragma unroll
            for (int st = 16; st > 0; st >>= 1) {
#pragma unroll
                for (int j = 0; j < 8; ++j) {
                    s[j]  += __shfl_xor_sync(0xffffffffu, s[j],  st);
                    q8[j] += __shfl_xor_sync(0xffffffffu, q8[j], st);
                }
            }
            if (lane == 0) {
#pragma unroll
                for (int j = 0; j < 8; ++j) { sSs[wid][j] = s[j]; sSq[wid][j] = q8[j]; }
            }
        } else {
            // fused final: sum 16-output groups (lanes 0-15 / 16-31)
#pragma unroll
            for (int st = 1; st < 16; st <<= 1) {
#pragma unroll
                for (int j = 0; j < 8; ++j)
                    h[j] += __shfl_xor_sync(0xffffffffu, h[j], st);
            }
            if ((lane & 15) == 0) {
                const int g = o >> 4;
#pragma unroll
                for (int j = 0; j < 8; ++j)
                    out[(bt * 8 + j) * 256 + g] = h[j] - 8.0f;
            }
        }
    } else if (HYB) {
        // ---- G path: warp-uniform full-row L2 gathers, GPER outputs/warp ----
        const int gw = wid - WS;
        const int obase = OS12 + (blk * WG + gw) * GPER;
        float sg[8], qg[8];
#pragma unroll
        for (int j = 0; j < 8; ++j) { sg[j] = 0.f; qg[j] = 0.f; }

        for (int k = 0; k < GPER; ++k) {
            const int o = obase + k;
            const uint4* pq = pkG + (o - OS12) * 32;
            float acc[8];
#pragma unroll
            for (int j = 0; j < 8; ++j) acc[j] = 0.f;
            uint4 qd = __ldg(pq);
#pragma unroll 2
            for (int q = 0; q < 32; ++q) {
                const uint4 qn = __ldg(pq + ((q + 1) & 31));
                const unsigned pc[4] = { qd.x, qd.y, qd.z, qd.w };
#pragma unroll
                for (int j = 0; j < 4; ++j) {
                    const int row = (int)(pc[j] & 0xFFFFu);
                    const float wv = __half2float(__ushort_as_half((unsigned short)(pc[j] >> 16)));
                    const uint4 v = __ldg(reinterpret_cast<const uint4*>(inRow + row * B) + lane);
                    fma8(v, wv, acc);
                }
                qd = qn;
            }
            const float bo = __ldg(bias + o);
            float c1 = 0.f, c2v = 0.f;
            if (L > 1) { c1 = g_C1b[o]; c2v = g_C2b[o]; }
            float h[8];
#pragma unroll
            for (int j = 0; j < 8; ++j) {
                const int col = lane * 8 + j;
                const float pre = (L > 1)
                    ? (fmaf(srs[col], acc[j] - smu[col] * c1, c2v) - bo)
                    : (acc[j] - bo);
                h[j] = sigmoidf_fast(pre);
                sg[j] += h[j];
                qg[j] = fmaf(h[j], h[j], qg[j]);
            }
            const uint4 ov = pack_h8(h);
            *reinterpret_cast<uint4*>(outR + o * B + lane * 8) = ov;
            reinterpret_cast<uint4*>(outB)[lane * OOUT + o] = ov;
        }
#pragma unroll
        for (int j = 0; j < 8; ++j) { sGs[gw][lane * 8 + j] = sg[j]; sGq[gw][lane * 8 + j] = qg[j]; }
    }
    __syncthreads();

    if (L < 3) {
        if (tid < B) {
            float s = 0.f, q = 0.f;
#pragma unroll
            for (int w = 0; w < WG; ++w) { s += sGs[w][tid]; q += sGq[w][tid]; }
            g_psG[blk * B + tid] = s;
            g_pqG[blk * B + tid] = q;
        }
        if (tid < 8) {
            float s = 0.f, q = 0.f;
#pragma unroll
            for (int w = 0; w < WS; ++w) { s += sSs[w][tid]; q += sSq[w][tid]; }
            g_psS[c * B + bt * 8 + tid] = s;
            g_pqS[c * B + bt * 8 + tid] = q;
        }
    }
}

// --- LN finalize ------------------------------------------------------------
template <int LI>
__global__ void k_fin() {
    const int t = threadIdx.x;
    float s = 0.f, q = 0.f;
#pragma unroll
    for (int cc = 0; cc < 4; ++cc) { s += g_psS[cc * B + t]; q += g_pqS[cc * B + t]; }
    for (int k = 0; k < NCTA; ++k) { s += g_psG[k * B + t]; q += g_pqG[k * B + t]; }
    const float inv = 1.0f / (float)O1;
    const float m = s * inv;
    const float var = q * inv - m * m;
    g_mu[LI][t] = m;
    g_rs[LI][t] = rsqrtf(var + 1e-12f);
}

// ---------------------------------------------------------------------------
extern "C" void kernel_launch(void* const* d_in, const int* in_sizes, int n_in,
                              void* d_out, int out_size) {
    (void)in_sizes; (void)n_in; (void)out_size;
    const float* x    = (const float*)d_in[0];
    const int*   sel1 = (const int*)  d_in[1];
    const float* w1   = (const float*)d_in[2];
    const float* b1   = (const float*)d_in[3];
    const float* g1   = (const float*)d_in[4];
    const float* be1  = (const float*)d_in[5];
    const int*   sel2 = (const int*)  d_in[6];
    const float* w2   = (const float*)d_in[7];
    const float* b2   = (const float*)d_in[8];
    const float* g2   = (const float*)d_in[9];
    const float* be2  = (const float*)d_in[10];
    const int*   sel3 = (const int*)  d_in[11];
    const float* w3   = (const float*)d_in[12];
    const float* b3   = (const float*)d_in[13];
    float* out = (float*)d_out;

    const int smem1 = IN1 * 16;   // 51200
    const int smem2 = O1 * 16;    // 131072
    cudaFuncSetAttribute(k_pop<1>, cudaFuncAttributeMaxDynamicSharedMemorySize, smem1);
    cudaFuncSetAttribute(k_pop<2>, cudaFuncAttributeMaxDynamicSharedMemorySize, smem2);
    cudaFuncSetAttribute(k_pop<3>, cudaFuncAttributeMaxDynamicSharedMemorySize, smem2);

    k_transpose<<<dim3(IN1 / 32, B / 32), dim3(32, 8)>>>(x);
    k_prep<<<640, 1024>>>(sel1, w1, sel2, w2, g1, be1, sel3, w3, g2, be2);

    k_pop<1><<<NCTA, 1024, smem1>>>(b1, nullptr);
    k_fin<0><<<1, 256>>>();
    k_pop<2><<<NCTA, 1024, smem2>>>(b2, nullptr);
    k_fin<1><<<1, 256>>>();
    k_pop<3><<<NCTA, 1024, smem2>>>(b3, out);
}

// round 11
// speedup vs baseline: 2.6034x; 2.6034x over previous
#include <cuda_runtime.h>
#include <cuda_fp16.h>

// ---------------------------------------------------------------------------
// Popcnt_14731737825611 — R7: consolidated warp-uniform L2-gather (R3 arch).
// Warp = 1 output; lanes cover 8 batch columns each (uint4 fp16 row loads,
// warp-uniform index -> fully coalesced 512B row reads at the LTS ceiling).
// Pair tables as uint4 quads (idx u16 | fp16 w). LayerNorm folded into the
// consumer via C1/C2; LN partials fused into pop epilogue; final group-sum
// fused into pop3 (one 512-thread block per output group). 7 launches.
// ---------------------------------------------------------------------------

namespace {
constexpr int B     = 256;
constexpr int IN1   = 3200;
constexpr int O1    = 8192;
constexpr int O3    = 4096;
constexpr int P     = 128;
constexpr int NSLOT = O1 / 8;     // 1024 partial slots (pop1/pop2 CTA count)
}

// Static device scratch.
__device__ __half g_xT[IN1 * B];
__device__ __half g_h1[O1 * B];
__device__ __half g_h2[O1 * B];
__device__ uint4  g_pk1[O1 * 32];
__device__ uint4  g_pk2[O1 * 32];
__device__ uint4  g_pk3[O3 * 32];
__device__ float  g_C1b[O1], g_C2b[O1], g_C1c[O3], g_C2c[O3];
__device__ float  g_ps[NSLOT * B], g_pq[NSLOT * B];
__device__ float  g_mu[2][B], g_rs[2][B];

__device__ __forceinline__ float sigmoidf_fast(float x) {
    return 1.0f / (1.0f + __expf(-x));
}
__device__ __forceinline__ unsigned pack_pair(int idx, float w) {
    __half h = __float2half_rn(w);
    return (unsigned)idx | ((unsigned)__half_as_ushort(h) << 16);
}
__device__ __forceinline__ float wgt(unsigned pc) {
    return __half2float(__ushort_as_half((unsigned short)(pc >> 16)));
}
__device__ __forceinline__ void fma8(const uint4 v, const float wv, float* acc) {
    float2 f;
    f = __half22float2(*(const __half2*)&v.x); acc[0] = fmaf(wv, f.x, acc[0]); acc[1] = fmaf(wv, f.y, acc[1]);
    f = __half22float2(*(const __half2*)&v.y); acc[2] = fmaf(wv, f.x, acc[2]); acc[3] = fmaf(wv, f.y, acc[3]);
    f = __half22float2(*(const __half2*)&v.z); acc[4] = fmaf(wv, f.x, acc[4]); acc[5] = fmaf(wv, f.y, acc[5]);
    f = __half22float2(*(const __half2*)&v.w); acc[6] = fmaf(wv, f.x, acc[6]); acc[7] = fmaf(wv, f.y, acc[7]);
}
__device__ __forceinline__ uint4 pack_h8(const float* h) {
    uint4 ov; __half2 hh;
    hh = __floats2half2_rn(h[0], h[1]); ov.x = *(unsigned*)&hh;
    hh = __floats2half2_rn(h[2], h[3]); ov.y = *(unsigned*)&hh;
    hh = __floats2half2_rn(h[4], h[5]); ov.z = *(unsigned*)&hh;
    hh = __floats2half2_rn(h[6], h[7]); ov.w = *(unsigned*)&hh;
    return ov;
}

// --- transpose x[B, IN1] -> g_xT[IN1, B] (fp16) ----------------------------
__global__ void k_transpose(const float* __restrict__ x) {
    __shared__ float t[32][33];
    const int i0 = blockIdx.x * 32;
    const int b0 = blockIdx.y * 32;
    const int tx = threadIdx.x, ty = threadIdx.y;
#pragma unroll
    for (int j = 0; j < 32; j += 8)
        t[ty + j][tx] = x[(b0 + ty + j) * IN1 + (i0 + tx)];
    __syncthreads();
#pragma unroll
    for (int j = 0; j < 32; j += 8)
        g_xT[(i0 + ty + j) * B + (b0 + tx)] = __float2half_rn(t[tx][ty + j]);
}

// --- merged prep: pack all pair tables, C1/C2 for layers 2/3 ---------------
// Warp = 1 output (32 quads, 1 per lane). Block 256 = 8 outputs.
__global__ void __launch_bounds__(256) k_prep(
    const int* __restrict__ sel1, const float* __restrict__ w1,
    const int* __restrict__ sel2, const float* __restrict__ w2,
    const float* __restrict__ g1v, const float* __restrict__ be1,
    const int* __restrict__ sel3, const float* __restrict__ w3,
    const float* __restrict__ g2v, const float* __restrict__ be2)
{
    const int gw   = blockIdx.x * 8 + (threadIdx.x >> 5);   // global warp slot
    const int lane = threadIdx.x & 31;

    int layer, o;
    const int* sel; const float* w; const float* gm; const float* bt;
    uint4* pk; float* C1; float* C2;
    if (gw < O1)           { layer = 1; o = gw;            sel = sel1; w = w1; gm = nullptr; bt = nullptr; pk = g_pk1; C1 = nullptr; C2 = nullptr; }
    else if (gw < 2 * O1)  { layer = 2; o = gw - O1;       sel = sel2; w = w2; gm = g1v;    bt = be1;     pk = g_pk2; C1 = g_C1b;  C2 = g_C2b; }
    else                   { layer = 3; o = gw - 2 * O1;   sel = sel3; w = w3; gm = g2v;    bt = be2;     pk = g_pk3; C1 = g_C1c;  C2 = g_C2c; }

    const int4   s4 = reinterpret_cast<const int4*>(sel + o * P)[lane];
    const float4 w4 = reinterpret_cast<const float4*>(w   + o * P)[lane];
    const int   idx[4] = { s4.x, s4.y, s4.z, s4.w };
    const float sg[4]  = { sigmoidf_fast(w4.x), sigmoidf_fast(w4.y),
                           sigmoidf_fast(w4.z), sigmoidf_fast(w4.w) };
    unsigned pc[4];
    float c1 = 0.f, c2 = 0.f;
#pragma unroll
    for (int j = 0; j < 4; ++j) {
        float sw = sg[j];
        if (layer > 1) {
            sw *= __ldg(gm + idx[j]);
            c1 += sw;
            c2 = fmaf(sg[j], __ldg(bt + idx[j]), c2);
        }
        pc[j] = pack_pair(idx[j], sw);
    }
    pk[o * 32 + lane] = make_uint4(pc[0], pc[1], pc[2], pc[3]);
    if (layer > 1) {
#pragma unroll
        for (int st = 16; st > 0; st >>= 1) {
            c1 += __shfl_xor_sync(0xffffffffu, c1, st);
            c2 += __shfl_xor_sync(0xffffffffu, c2, st);
        }
        if (lane == 0) { C1[o] = c1; C2[o] = c2; }
    }
}

// --- popcnt layer: warp = 1 output, lane = 8 batch columns -----------------
// L=1,2: block 256 (8 warps), grid O1/8; fused LN partial per CTA.
// L=3:   block 512 (16 warps = one output group), grid O3/16; fused final.
template <int L>
__global__ void __launch_bounds__((L == 3) ? 512 : 256) k_pop(
    const float* __restrict__ bias, float* __restrict__ out)
{
    constexpr int WARPS = (L == 3) ? 16 : 8;
    __shared__ float sh[WARPS][B];

    const __half* inT  = (L == 1) ? g_xT  : (L == 2) ? g_h1  : g_h2;
    const uint4*  pk   = (L == 1) ? g_pk1 : (L == 2) ? g_pk2 : g_pk3;
    __half*       outT = (L == 1) ? g_h1  : g_h2;

    const int tid  = threadIdx.x;
    const int wid  = tid >> 5;
    const int lane = tid & 31;
    const int o    = blockIdx.x * WARPS + wid;

    const uint4* pq = pk + o * 32;
    uint4 qd = __ldg(pq);
    float acc[8];
#pragma unroll
    for (int j = 0; j < 8; ++j) acc[j] = 0.f;

#pragma unroll 4
    for (int q = 0; q < 32; ++q) {
        const uint4 qn = __ldg(pq + ((q + 1) & 31));
        const unsigned p0 = qd.x, p1 = qd.y, p2 = qd.z, p3 = qd.w;
        const uint4 v0 = *(reinterpret_cast<const uint4*>(inT + (p0 & 0xFFFFu) * B) + lane);
        const uint4 v1 = *(reinterpret_cast<const uint4*>(inT + (p1 & 0xFFFFu) * B) + lane);
        const uint4 v2 = *(reinterpret_cast<const uint4*>(inT + (p2 & 0xFFFFu) * B) + lane);
        const uint4 v3 = *(reinterpret_cast<const uint4*>(inT + (p3 & 0xFFFFu) * B) + lane);
        fma8(v0, wgt(p0), acc);
        fma8(v1, wgt(p1), acc);
        fma8(v2, wgt(p2), acc);
        fma8(v3, wgt(p3), acc);
        qd = qn;
    }

    // epilogue: (folded input-LN) + bias + sigmoid
    const float bo = __ldg(bias + o);
    float h[8];
    if (L > 1) {
        const float c1  = ((L == 2) ? g_C1b : g_C1c)[o];
        const float c2v = ((L == 2) ? g_C2b : g_C2c)[o];
        const float4 mA = *reinterpret_cast<const float4*>(&g_mu[L - 2][lane * 8]);
        const float4 mB = *reinterpret_cast<const float4*>(&g_mu[L - 2][lane * 8 + 4]);
        const float4 rA = *reinterpret_cast<const float4*>(&g_rs[L - 2][lane * 8]);
        const float4 rB = *reinterpret_cast<const float4*>(&g_rs[L - 2][lane * 8 + 4]);
        const float mu[8] = { mA.x, mA.y, mA.z, mA.w, mB.x, mB.y, mB.z, mB.w };
        const float rs[8] = { rA.x, rA.y, rA.z, rA.w, rB.x, rB.y, rB.z, rB.w };
#pragma unroll
        for (int j = 0; j < 8; ++j)
            h[j] = sigmoidf_fast(fmaf(rs[j], acc[j] - mu[j] * c1, c2v) - bo);
    } else {
#pragma unroll
        for (int j = 0; j < 8; ++j)
            h[j] = sigmoidf_fast(acc[j] - bo);
    }

    if (L < 3) {
        // store activations + stage h for LN partial reduce
        *(reinterpret_cast<uint4*>(outT + o * B) + lane) = pack_h8(h);
#pragma unroll
        for (int j = 0; j < 8; ++j) sh[wid][lane * 8 + j] = h[j];
        __syncthreads();
        // one partial (sum, sumsq) per CTA per batch column
        {
            float s = 0.f, qv = 0.f;
#pragma unroll
            for (int w = 0; w < WARPS; ++w) {
                const float v = sh[w][tid];
                s += v;
                qv = fmaf(v, v, qv);
            }
            g_ps[blockIdx.x * B + tid] = s;
            g_pq[blockIdx.x * B + tid] = qv;
        }
    } else {
        // fused final: this block IS one output group of 16
#pragma unroll
        for (int j = 0; j < 8; ++j) sh[wid][lane * 8 + j] = h[j];
        __syncthreads();
        if (tid < B) {
            float s = 0.f;
#pragma unroll
            for (int w = 0; w < 16; ++w) s += sh[w][tid];
            out[tid * 256 + blockIdx.x] = s - 8.0f;
        }
    }
}

// --- LN finalize: block per batch column, reduce NSLOT partials ------------
template <int LI>
__global__ void k_fin() {
    __shared__ float ss[256], sq[256];
    const int col = blockIdx.x;
    const int t   = threadIdx.x;
    float s = 0.f, q = 0.f;
#pragma unroll
    for (int k = 0; k < NSLOT / 256; ++k) {
        s += g_ps[(t + k * 256) * B + col];
        q += g_pq[(t + k * 256) * B + col];
    }
    ss[t] = s; sq[t] = q;
    __syncthreads();
    for (int st = 128; st > 0; st >>= 1) {
        if (t < st) { ss[t] += ss[t + st]; sq[t] += sq[t + st]; }
        __syncthreads();
    }
    if (t == 0) {
        const float inv = 1.0f / (float)O1;
        const float m   = ss[0] * inv;
        const float var = sq[0] * inv - m * m;
        g_mu[LI][col] = m;
        g_rs[LI][col] = rsqrtf(var + 1e-12f);
    }
}

// ---------------------------------------------------------------------------
extern "C" void kernel_launch(void* const* d_in, const int* in_sizes, int n_in,
                              void* d_out, int out_size) {
    (void)in_sizes; (void)n_in; (void)out_size;
    const float* x    = (const float*)d_in[0];
    const int*   sel1 = (const int*)  d_in[1];
    const float* w1   = (const float*)d_in[2];
    const float* b1   = (const float*)d_in[3];
    const float* g1   = (const float*)d_in[4];
    const float* be1  = (const float*)d_in[5];
    const int*   sel2 = (const int*)  d_in[6];
    const float* w2   = (const float*)d_in[7];
    const float* b2   = (const float*)d_in[8];
    const float* g2   = (const float*)d_in[9];
    const float* be2  = (const float*)d_in[10];
    const int*   sel3 = (const int*)  d_in[11];
    const float* w3   = (const float*)d_in[12];
    const float* b3   = (const float*)d_in[13];
    float* out = (float*)d_out;

    k_transpose<<<dim3(IN1 / 32, B / 32), dim3(32, 8)>>>(x);
    k_prep<<<(2 * O1 + O3) / 8, 256>>>(sel1, w1, sel2, w2, g1, be1,
                                       sel3, w3, g2, be2);

    k_pop<1><<<O1 / 8, 256>>>(b1, nullptr);
    k_fin<0><<<B, 256>>>();
    k_pop<2><<<O1 / 8, 256>>>(b2, nullptr);
    k_fin<1><<<B, 256>>>();
    k_pop<3><<<O3 / 16, 512>>>(b3, out);
}